// round 17
// baseline (speedup 1.0000x reference)
#include <cuda_runtime.h>
#include <cstdint>

#define C 128
#define G 100000
#define NPTS_MAX 1000000
#define SLOTS 32   // per-group direct slots; beyond -> overflow list (P ~ 5e-10)

// Scratch (device globals — zero-init at load; self-cleaning per run).
__device__ int g_hist[G];            // per-group counts (self-cleaned)
__device__ int g_slot[G * SLOTS];    // member ids, slot = g*32 + rank
__device__ int g_ovf[G];             // overflow list head, 0 = empty (self-cleaned)
__device__ int g_next[NPTS_MAX];     // overflow chain (encoded +1)

__device__ __forceinline__ int clampg(int g) { return min(max(g, 0), G - 1); }

__device__ __forceinline__ void build_one(int g, int p) {
    int r = atomicAdd(&g_hist[g], 1);
    if (r < SLOTS) {
        g_slot[g * SLOTS + r] = p;
    } else {
        g_next[p] = atomicExch(&g_ovf[g], p + 1);   // rare spill
    }
}

// ---------------------------------------------------------------------------
// 1) ONE-PASS build: rank via returning atomic + direct slot store.
// ---------------------------------------------------------------------------
__global__ void __launch_bounds__(256) build_kernel(
    const int* __restrict__ gid, int n4, int n)
{
    int i = blockIdx.x * blockDim.x + threadIdx.x;
    if (i < n4) {
        int4 g4 = __ldcs(reinterpret_cast<const int4*>(gid) + i);  // single-use stream
        int p = i * 4;
        build_one(clampg(g4.x), p);
        build_one(clampg(g4.y), p + 1);
        build_one(clampg(g4.z), p + 2);
        build_one(clampg(g4.w), p + 3);
    }
    int t = n4 * 4 + i;
    if (i < (n - n4 * 4)) {
        build_one(clampg(gid[t]), t);
    }
}

// ---------------------------------------------------------------------------
// 2) reduce + broadcast write. One warp per group; 32 lanes hold all 128
//    channels as float4 in registers. Member ids: one aligned 128B coalesced
//    load + shfl broadcast. Streaming hints: feat read __ldcs, out write
//    __stcs (both single-use; keep L2 for slot/hist metadata).
//    SELF-CLEAN: hist (and ovf head if used) zeroed after consumption.
// ---------------------------------------------------------------------------
__global__ void __launch_bounds__(256) reduce_write_kernel(
    const float* __restrict__ feat,
    float* __restrict__ out)
{
    int warp = (blockIdx.x * blockDim.x + threadIdx.x) >> 5;
    int lane = threadIdx.x & 31;
    if (warp >= G) return;

    int cnt = g_hist[warp];                  // broadcast load
    if (cnt == 0) return;                    // empty: already clean
    if (lane == 0) g_hist[warp] = 0;         // self-clean for next replay

    int m = min(cnt, SLOTS);
    int idx = 0;
    if (lane < m) idx = g_slot[warp * SLOTS + lane];   // one 128B line

    float4 acc = make_float4(0.f, 0.f, 0.f, 0.f);

    #pragma unroll 8
    for (int j = 0; j < m; j++) {
        int p = __shfl_sync(0xffffffffu, idx, j);
        float4 v = __ldcs(reinterpret_cast<const float4*>(feat + (size_t)p * C) + lane);
        acc.x += v.x; acc.y += v.y; acc.z += v.z; acc.w += v.w;
    }

    int ovf_head = 0;
    if (cnt > SLOTS) {                       // practically never
        ovf_head = g_ovf[warp];
        if (lane == 0) g_ovf[warp] = 0;      // self-clean
        int p = ovf_head;
        while (p != 0) {
            int q = p - 1;
            float4 v = __ldcs(reinterpret_cast<const float4*>(feat + (size_t)q * C) + lane);
            acc.x += v.x; acc.y += v.y; acc.z += v.z; acc.w += v.w;
            int np = 0;
            if (lane == 0) np = g_next[q];
            p = __shfl_sync(0xffffffffu, np, 0);
        }
    }

    float inv = 1.0f / (float)cnt;
    acc.x *= inv; acc.y *= inv; acc.z *= inv; acc.w *= inv;

    #pragma unroll 8
    for (int j = 0; j < m; j++) {
        int q = __shfl_sync(0xffffffffu, idx, j);
        __stcs(reinterpret_cast<float4*>(out + (size_t)q * C) + lane, acc);
    }

    if (cnt > SLOTS) {
        int p = ovf_head;
        while (p != 0) {
            int q = p - 1;
            __stcs(reinterpret_cast<float4*>(out + (size_t)q * C) + lane, acc);
            int np = 0;
            if (lane == 0) np = g_next[q];
            p = __shfl_sync(0xffffffffu, np, 0);
        }
    }
}

// ---------------------------------------------------------------------------
// Launch. Inputs: [0] ref_bxyz (unused), [1] ref_feat f32 [N,128],
// [2] group_ids int32 [N]. Output: [N,128] f32.
// ---------------------------------------------------------------------------
extern "C" void kernel_launch(void* const* d_in, const int* in_sizes, int n_in,
                              void* d_out, int out_size) {
    const float* feat = (const float*)d_in[1];
    const int* gid = (const int*)d_in[2];
    float* out = (float*)d_out;

    const int n = in_sizes[2];  // 1M points
    const int n4 = n / 4;

    build_kernel<<<(n4 + 255) / 256, 256>>>(gid, n4, n);

    // one warp per group, 8 warps per block
    reduce_write_kernel<<<(G + 7) / 8, 256>>>(feat, out);
}